// round 1
// baseline (speedup 1.0000x reference)
#include <cuda_runtime.h>

#define Bz 2
#define Vn 4
#define Cn 32
#define Hf 64
#define Wf 64
#define Dv 64
#define Pn (Dv*Dv*Dv)        // 262144 points per batch

// Scratch: transposed features [BV][H][W][C] (channels contiguous -> coalesced taps)
__device__ float g_featT[Bz*Vn*Hf*Wf*Cn];
// Per-camera constants: R[9], newT[3], fx, fy, cx, cy
__device__ float g_cam[Bz*Vn][16];

// ---------------------------------------------------------------------------
// Tiny setup: fold root_world into camera translation, gather K entries.
// ---------------------------------------------------------------------------
__global__ void cam_setup(const float* __restrict__ R, const float* __restrict__ T,
                          const float* __restrict__ K, const float* __restrict__ root) {
    int i = threadIdx.x;
    if (i >= Bz*Vn) return;
    int b = i / Vn;
    const float* Ri = R + i*9;
    const float* Ti = T + i*3;
    const float* Ki = K + i*9;
    const float* rb = root + b*3;
    float* o = g_cam[i];
    #pragma unroll
    for (int r = 0; r < 9; r++) o[r] = Ri[r];
    #pragma unroll
    for (int r = 0; r < 3; r++)
        o[9+r] = Ri[r*3+0]*rb[0] + Ri[r*3+1]*rb[1] + Ri[r*3+2]*rb[2] + Ti[r];
    o[12] = Ki[0];  // fx
    o[13] = Ki[4];  // fy
    o[14] = Ki[2];  // cx
    o[15] = Ki[5];  // cy
}

// ---------------------------------------------------------------------------
// Transpose features [BV,C,H,W] -> [BV,H,W,C] (dest-coalesced writes).
// ---------------------------------------------------------------------------
__global__ void transpose_feat(const float* __restrict__ f) {
    int idx = blockIdx.x * blockDim.x + threadIdx.x;   // over 1,048,576 elems
    int c   = idx & 31;
    int pix = (idx >> 5) & (Hf*Wf - 1);
    int bv  = idx >> 17;                               // / (4096*32)
    g_featT[idx] = f[(bv*Cn + c)*(Hf*Wf) + pix];
}

// ---------------------------------------------------------------------------
// Main kernel: block = 64 points. Phase 1: 256 threads compute 64 pts x 4
// views of projections (tap offsets + validity-masked weights -> SMEM).
// Phase 2: warp-per-point, lane=channel, 16 coalesced 128B gathers/point.
// ---------------------------------------------------------------------------
__global__ __launch_bounds__(256) void sample_kernel(float* __restrict__ out) {
    __shared__ int4   s_off[64][Vn];   // tap pixel offsets y*W+x (clamped)
    __shared__ float4 s_w[64][Vn];     // tap weights with validity folded in

    const int tid   = threadIdx.x;
    const int b     = blockIdx.x >> 12;          // 4096 blocks per batch
    const int pbase = (blockIdx.x & 4095) * 64;

    // -------- Phase 1: projection, one (point,view) per thread --------
    {
        const int pl = tid >> 2;        // local point 0..63
        const int v  = tid & 3;         // view
        const int p  = pbase + pl;
        const int xi = p & 63, yi = (p >> 6) & 63, zi = p >> 12;

        // world coords: (idx/(D-1) - 0.5) * SPACE
        const float wx = (xi * (1.0f/63.0f) - 0.5f) * 0.2f;
        const float wy = (yi * (1.0f/63.0f) - 0.5f) * 0.2f;
        const float wz = (zi * (1.0f/63.0f) - 0.5f) * 0.2f;

        const float* cam = g_cam[b*Vn + v];
        const float Xc = cam[0]*wx + cam[1]*wy + cam[2]*wz + cam[9];
        const float Yc = cam[3]*wx + cam[4]*wy + cam[5]*wz + cam[10];
        const float Zc = cam[6]*wx + cam[7]*wy + cam[8]*wz + cam[11];
        const float zc = fmaxf(Zc, 1e-5f);

        const float u  = (Xc * cam[12]) / zc + cam[14];
        const float vv = (Yc * cam[13]) / zc + cam[15];
        // px = u*Wf/255 - 0.5 (unnormalized grid_sample coord, align_corners=False)
        const float px = u  * (64.0f/255.0f) - 0.5f;
        const float py = vv * (64.0f/255.0f) - 0.5f;

        const float x0f = floorf(px), y0f = floorf(py);
        const float fx1 = px - x0f,   fy1 = py - y0f;
        const float fx0 = 1.0f - fx1, fy0 = 1.0f - fy1;
        const int x0 = (int)x0f, y0 = (int)y0f;
        const int x1 = x0 + 1,   y1 = y0 + 1;

        // validity folded into factorized weights (zero-padding semantics)
        const float mx0 = (x0 >= 0 && x0 < Wf) ? fx0 : 0.0f;
        const float mx1 = (x1 >= 0 && x1 < Wf) ? fx1 : 0.0f;
        const float my0 = (y0 >= 0 && y0 < Hf) ? fy0 : 0.0f;
        const float my1 = (y1 >= 0 && y1 < Hf) ? fy1 : 0.0f;

        const int x0c = min(max(x0, 0), Wf-1), x1c = min(max(x1, 0), Wf-1);
        const int y0c = min(max(y0, 0), Hf-1), y1c = min(max(y1, 0), Hf-1);

        s_off[pl][v] = make_int4(y0c*Wf + x0c, y0c*Wf + x1c,
                                 y1c*Wf + x0c, y1c*Wf + x1c);
        s_w[pl][v]   = make_float4(mx0*my0, mx1*my0, mx0*my1, mx1*my1);
    }
    __syncthreads();

    // -------- Phase 2: gather + accumulate, warp-per-point, lane=channel ----
    const int w    = tid >> 5;
    const int lane = tid & 31;
    const float* fb = g_featT + (size_t)(b*Vn) * (Hf*Wf*Cn) + lane;
    float* ob = out + ((size_t)b*Cn + lane) * Pn + pbase;

    #pragma unroll
    for (int i = 0; i < 8; i++) {
        const int pl = w*8 + i;
        float acc = 0.0f;
        #pragma unroll
        for (int v = 0; v < Vn; v++) {
            const int4   off = s_off[pl][v];   // broadcast LDS (same addr all lanes)
            const float4 wt  = s_w[pl][v];
            const float* fv  = fb + v * (Hf*Wf*Cn);
            acc = fmaf(wt.x, __ldg(fv + off.x*Cn), acc);
            acc = fmaf(wt.y, __ldg(fv + off.y*Cn), acc);
            acc = fmaf(wt.z, __ldg(fv + off.z*Cn), acc);
            acc = fmaf(wt.w, __ldg(fv + off.w*Cn), acc);
        }
        ob[pl] = acc * 0.25f;   // mean over views
    }
}

// ---------------------------------------------------------------------------
extern "C" void kernel_launch(void* const* d_in, const int* in_sizes, int n_in,
                              void* d_out, int out_size) {
    const float* feat = (const float*)d_in[0];   // [2,4,32,64,64]
    const float* R    = (const float*)d_in[1];   // [2,4,3,3]
    const float* T    = (const float*)d_in[2];   // [2,4,3]
    const float* K    = (const float*)d_in[3];   // [2,4,3,3]
    const float* root = (const float*)d_in[4];   // [2,3]
    float* out = (float*)d_out;                  // [2,32,64,64,64]

    cam_setup<<<1, 32>>>(R, T, K, root);
    transpose_feat<<<(Bz*Vn*Hf*Wf*Cn)/256, 256>>>(feat);
    sample_kernel<<<Bz*Pn/64, 256>>>(out);
}

// round 2
// speedup vs baseline: 1.7987x; 1.7987x over previous
#include <cuda_runtime.h>

#define Bz 2
#define Vn 4
#define Cn 32
#define Hf 64
#define Wf 64
#define Dv 64
#define Pn (Dv*Dv*Dv)        // 262144 points per batch

// Tile: 16 (x) x 4 (y) x 2 (z) = 128 points per block, 512 threads.
#define TX 16
#define TY 4
#define TZ 2
#define TP (TX*TY*TZ)        // 128

// Scratch: transposed features [BV][H][W][C]
__device__ float g_featT[Bz*Vn*Hf*Wf*Cn];
// Per-camera: R[9], newT[3], fx, fy, cx, cy
__device__ float g_cam[Bz*Vn][16];

// ---------------------------------------------------------------------------
// Transpose [BV,C,H,W] -> [BV,H,W,C]; block 0 also folds camera constants.
// ---------------------------------------------------------------------------
__global__ void prep_kernel(const float* __restrict__ f,
                            const float* __restrict__ R, const float* __restrict__ T,
                            const float* __restrict__ K, const float* __restrict__ root) {
    int idx = blockIdx.x * blockDim.x + threadIdx.x;
    int c   = idx & 31;
    int pix = (idx >> 5) & (Hf*Wf - 1);
    int bv  = idx >> 17;
    g_featT[idx] = f[(bv*Cn + c)*(Hf*Wf) + pix];

    if (blockIdx.x == 0 && threadIdx.x < Bz*Vn) {
        int i = threadIdx.x, b = i / Vn;
        const float* Ri = R + i*9; const float* Ti = T + i*3;
        const float* Ki = K + i*9; const float* rb = root + b*3;
        float* o = g_cam[i];
        #pragma unroll
        for (int r = 0; r < 9; r++) o[r] = Ri[r];
        #pragma unroll
        for (int r = 0; r < 3; r++)
            o[9+r] = Ri[r*3+0]*rb[0] + Ri[r*3+1]*rb[1] + Ri[r*3+2]*rb[2] + Ti[r];
        o[12] = Ki[0]; o[13] = Ki[4]; o[14] = Ki[2]; o[15] = Ki[5];
    }
}

// ---------------------------------------------------------------------------
// Main kernel. Phase 1: 512 threads project 128 pts x 4 views -> SMEM taps.
// Phase 2: warp-per-point (lane=channel), 16 coalesced 128B gathers/point,
//          accumulate into SMEM staging.
// Phase 3: coalesced float4 stores along x.
// ---------------------------------------------------------------------------
__global__ __launch_bounds__(512) void sample_kernel(float* __restrict__ out) {
    __shared__ int4   s_off[TP][Vn];
    __shared__ float4 s_w[TP][Vn];
    __shared__ float  s_acc[TP][Cn + 1];   // pad -> conflict-free

    const int tid = threadIdx.x;
    const int bid = blockIdx.x;
    const int b   = bid >> 11;                 // 2048 tiles per batch
    const int t   = bid & 2047;
    const int x0t = (t & 3) * TX;              // 4 x-tiles
    const int y0t = ((t >> 2) & 15) * TY;      // 16 y-tiles
    const int z0t = (t >> 6) * TZ;             // 32 z-tiles

    // -------- Phase 1: projection (one (point,view) per thread) --------
    {
        const int pl = tid >> 2;
        const int v  = tid & 3;
        const int xi = x0t + (pl & 15);
        const int yi = y0t + ((pl >> 4) & 3);
        const int zi = z0t + (pl >> 6);

        const float wx = (xi * (1.0f/63.0f) - 0.5f) * 0.2f;
        const float wy = (yi * (1.0f/63.0f) - 0.5f) * 0.2f;
        const float wz = (zi * (1.0f/63.0f) - 0.5f) * 0.2f;

        const float* cam = g_cam[b*Vn + v];
        const float Xc = cam[0]*wx + cam[1]*wy + cam[2]*wz + cam[9];
        const float Yc = cam[3]*wx + cam[4]*wy + cam[5]*wz + cam[10];
        const float Zc = cam[6]*wx + cam[7]*wy + cam[8]*wz + cam[11];
        const float zc = fmaxf(Zc, 1e-5f);

        const float u  = (Xc * cam[12]) / zc + cam[14];
        const float vv = (Yc * cam[13]) / zc + cam[15];
        const float px = u  * (64.0f/255.0f) - 0.5f;
        const float py = vv * (64.0f/255.0f) - 0.5f;

        const float x0f = floorf(px), y0f = floorf(py);
        const float fx1 = px - x0f,   fy1 = py - y0f;
        const float fx0 = 1.0f - fx1, fy0 = 1.0f - fy1;
        const int ix0 = (int)x0f, iy0 = (int)y0f;
        const int ix1 = ix0 + 1,  iy1 = iy0 + 1;

        const float mx0 = (ix0 >= 0 && ix0 < Wf) ? fx0 : 0.0f;
        const float mx1 = (ix1 >= 0 && ix1 < Wf) ? fx1 : 0.0f;
        const float my0 = (iy0 >= 0 && iy0 < Hf) ? fy0 : 0.0f;
        const float my1 = (iy1 >= 0 && iy1 < Hf) ? fy1 : 0.0f;

        const int x0c = min(max(ix0, 0), Wf-1), x1c = min(max(ix1, 0), Wf-1);
        const int y0c = min(max(iy0, 0), Hf-1), y1c = min(max(iy1, 0), Hf-1);

        s_off[pl][v] = make_int4(y0c*Wf + x0c, y0c*Wf + x1c,
                                 y1c*Wf + x0c, y1c*Wf + x1c);
        s_w[pl][v]   = make_float4(mx0*my0, mx1*my0, mx0*my1, mx1*my1);
    }
    __syncthreads();

    // -------- Phase 2: gather + accumulate --------
    {
        const int w    = tid >> 5;
        const int lane = tid & 31;
        const float* fb = g_featT + (size_t)(b*Vn) * (Hf*Wf*Cn) + lane;

        #pragma unroll
        for (int i = 0; i < 8; i++) {
            const int pl = w*8 + i;
            float acc = 0.0f;
            #pragma unroll
            for (int v = 0; v < Vn; v++) {
                const int4   off = s_off[pl][v];
                const float4 wt  = s_w[pl][v];
                const float* fv  = fb + v * (Hf*Wf*Cn);
                acc = fmaf(wt.x, __ldg(fv + off.x*Cn), acc);
                acc = fmaf(wt.y, __ldg(fv + off.y*Cn), acc);
                acc = fmaf(wt.z, __ldg(fv + off.z*Cn), acc);
                acc = fmaf(wt.w, __ldg(fv + off.w*Cn), acc);
            }
            s_acc[pl][lane] = acc * 0.25f;
        }
    }
    __syncthreads();

    // -------- Phase 3: coalesced stores (float4 along x) --------
    #pragma unroll
    for (int q = 0; q < 2; q++) {
        const int idx = q*512 + tid;           // [0,1024): 32c x 2z x 4y x 4 xq
        const int xq = idx & 3;
        const int yl = (idx >> 2) & 3;
        const int zl = (idx >> 4) & 1;
        const int c  = idx >> 5;
        const int plb = zl*64 + yl*16 + xq*4;
        float4 v;
        v.x = s_acc[plb+0][c];
        v.y = s_acc[plb+1][c];
        v.z = s_acc[plb+2][c];
        v.w = s_acc[plb+3][c];
        const int pg = (z0t+zl)*4096 + (y0t+yl)*64 + x0t + xq*4;
        *reinterpret_cast<float4*>(out + ((size_t)(b*Cn + c) << 18) + pg) = v;
    }
}

// ---------------------------------------------------------------------------
extern "C" void kernel_launch(void* const* d_in, const int* in_sizes, int n_in,
                              void* d_out, int out_size) {
    const float* feat = (const float*)d_in[0];
    const float* R    = (const float*)d_in[1];
    const float* T    = (const float*)d_in[2];
    const float* K    = (const float*)d_in[3];
    const float* root = (const float*)d_in[4];
    float* out = (float*)d_out;

    prep_kernel<<<(Bz*Vn*Hf*Wf*Cn)/256, 256>>>(feat, R, T, K, root);
    sample_kernel<<<Bz*Pn/TP, 512>>>(out);
}

// round 3
// speedup vs baseline: 1.8939x; 1.0529x over previous
#include <cuda_runtime.h>

#define Bz 2
#define Vn 4
#define Cn 32
#define Hf 64
#define Wf 64
#define Dv 64
#define Pn (Dv*Dv*Dv)        // 262144 points per batch

// Tile: 16 (x) x 4 (y) x 2 (z) = 128 points per block, 512 threads.
#define TX 16
#define TY 4
#define TZ 2
#define TP (TX*TY*TZ)        // 128

__device__ float g_featT[Bz*Vn*Hf*Wf*Cn];   // [BV][H][W][C]
__device__ float g_cam[Bz*Vn][16];

// ---------------------------------------------------------------------------
__global__ void prep_kernel(const float* __restrict__ f,
                            const float* __restrict__ R, const float* __restrict__ T,
                            const float* __restrict__ K, const float* __restrict__ root) {
    int idx = blockIdx.x * blockDim.x + threadIdx.x;
    int c   = idx & 31;
    int pix = (idx >> 5) & (Hf*Wf - 1);
    int bv  = idx >> 17;
    g_featT[idx] = f[(bv*Cn + c)*(Hf*Wf) + pix];

    if (blockIdx.x == 0 && threadIdx.x < Bz*Vn) {
        int i = threadIdx.x, b = i / Vn;
        const float* Ri = R + i*9; const float* Ti = T + i*3;
        const float* Ki = K + i*9; const float* rb = root + b*3;
        float* o = g_cam[i];
        #pragma unroll
        for (int r = 0; r < 9; r++) o[r] = Ri[r];
        #pragma unroll
        for (int r = 0; r < 3; r++)
            o[9+r] = Ri[r*3+0]*rb[0] + Ri[r*3+1]*rb[1] + Ri[r*3+2]*rb[2] + Ti[r];
        o[12] = Ki[0]; o[13] = Ki[4]; o[14] = Ki[2]; o[15] = Ki[5];
    }
}

// ---------------------------------------------------------------------------
__global__ __launch_bounds__(512, 2) void sample_kernel(float* __restrict__ out) {
    __shared__ int4   s_off[TP][Vn];        // tap offsets, pre-scaled by Cn
    __shared__ float4 s_w[TP][Vn];          // weights * 0.25 (view mean folded)
    __shared__ float  s_acc[TP][Cn];        // rotation-swizzled staging

    const int tid = threadIdx.x;
    const int bid = blockIdx.x;
    const int b   = bid >> 11;
    const int t   = bid & 2047;
    const int x0t = (t & 3) * TX;
    const int y0t = ((t >> 2) & 15) * TY;
    const int z0t = (t >> 6) * TZ;

    // -------- Phase 1: projection (one (point,view) per thread) --------
    {
        const int pl = tid >> 2;
        const int v  = tid & 3;
        const int xi = x0t + (pl & 15);
        const int yi = y0t + ((pl >> 4) & 3);
        const int zi = z0t + (pl >> 6);

        const float wx = (xi * (1.0f/63.0f) - 0.5f) * 0.2f;
        const float wy = (yi * (1.0f/63.0f) - 0.5f) * 0.2f;
        const float wz = (zi * (1.0f/63.0f) - 0.5f) * 0.2f;

        const float* cam = g_cam[b*Vn + v];
        const float Xc = cam[0]*wx + cam[1]*wy + cam[2]*wz + cam[9];
        const float Yc = cam[3]*wx + cam[4]*wy + cam[5]*wz + cam[10];
        const float Zc = cam[6]*wx + cam[7]*wy + cam[8]*wz + cam[11];
        const float zc = fmaxf(Zc, 1e-5f);

        const float u  = (Xc * cam[12]) / zc + cam[14];
        const float vv = (Yc * cam[13]) / zc + cam[15];
        const float px = u  * (64.0f/255.0f) - 0.5f;
        const float py = vv * (64.0f/255.0f) - 0.5f;

        const float x0f = floorf(px), y0f = floorf(py);
        const float fx1 = px - x0f,   fy1 = py - y0f;
        const float fx0 = 1.0f - fx1, fy0 = 1.0f - fy1;
        const int ix0 = (int)x0f, iy0 = (int)y0f;
        const int ix1 = ix0 + 1,  iy1 = iy0 + 1;

        const float mx0 = (ix0 >= 0 && ix0 < Wf) ? fx0 : 0.0f;
        const float mx1 = (ix1 >= 0 && ix1 < Wf) ? fx1 : 0.0f;
        const float my0 = (iy0 >= 0 && iy0 < Hf) ? fy0 * 0.25f : 0.0f;
        const float my1 = (iy1 >= 0 && iy1 < Hf) ? fy1 * 0.25f : 0.0f;

        const int x0c = min(max(ix0, 0), Wf-1), x1c = min(max(ix1, 0), Wf-1);
        const int y0c = min(max(iy0, 0), Hf-1), y1c = min(max(iy1, 0), Hf-1);

        s_off[pl][v] = make_int4((y0c*Wf + x0c)*Cn, (y0c*Wf + x1c)*Cn,
                                 (y1c*Wf + x0c)*Cn, (y1c*Wf + x1c)*Cn);
        s_w[pl][v]   = make_float4(mx0*my0, mx1*my0, mx0*my1, mx1*my1);
    }
    __syncthreads();

    // -------- Phase 2: gather with tap-register reuse (v outer, pt inner) ---
    {
        const int w    = tid >> 5;
        const int lane = tid & 31;
        float acc[8] = {0.f,0.f,0.f,0.f,0.f,0.f,0.f,0.f};

        for (int v = 0; v < Vn; v++) {
            const float* fv = g_featT + (size_t)(b*Vn + v) * (Hf*Wf*Cn) + lane;
            int prevx = -1, prevw = -1;
            float t0 = 0.f, t1 = 0.f, t2 = 0.f, t3 = 0.f;
            #pragma unroll
            for (int i = 0; i < 8; i++) {
                const int pl = w*8 + i;
                const int4   off = s_off[pl][v];   // warp-uniform broadcast
                const float4 wt  = s_w[pl][v];
                if (off.x != prevx || off.w != prevw) {   // uniform branch
                    t0 = __ldg(fv + off.x);
                    t1 = __ldg(fv + off.y);
                    t2 = __ldg(fv + off.z);
                    t3 = __ldg(fv + off.w);
                    prevx = off.x; prevw = off.w;
                }
                acc[i] = fmaf(wt.x, t0,
                         fmaf(wt.y, t1,
                         fmaf(wt.z, t2,
                         fmaf(wt.w, t3, acc[i]))));
            }
        }
        #pragma unroll
        for (int i = 0; i < 8; i++) {
            const int pl = w*8 + i;
            s_acc[pl][(lane + (pl >> 2)) & 31] = acc[i];   // rotation swizzle
        }
    }
    __syncthreads();

    // -------- Phase 3: conflict-free transpose + coalesced float4 stores ----
    #pragma unroll
    for (int q = 0; q < 2; q++) {
        const int idx = q*512 + tid;
        const int xq = idx & 3;
        const int yl = (idx >> 2) & 3;
        const int zl = (idx >> 4) & 1;
        const int c  = idx >> 5;
        const int plb = zl*64 + yl*16 + xq*4;
        const int m   = plb >> 2;                // xq + 4*yl + 16*zl, distinct/lane
        const int col = (c + m) & 31;
        float4 v;
        v.x = s_acc[plb+0][col];
        v.y = s_acc[plb+1][col];
        v.z = s_acc[plb+2][col];
        v.w = s_acc[plb+3][col];
        const int pg = (z0t+zl)*4096 + (y0t+yl)*64 + x0t + xq*4;
        *reinterpret_cast<float4*>(out + ((size_t)(b*Cn + c) << 18) + pg) = v;
    }
}

// ---------------------------------------------------------------------------
extern "C" void kernel_launch(void* const* d_in, const int* in_sizes, int n_in,
                              void* d_out, int out_size) {
    const float* feat = (const float*)d_in[0];
    const float* R    = (const float*)d_in[1];
    const float* T    = (const float*)d_in[2];
    const float* K    = (const float*)d_in[3];
    const float* root = (const float*)d_in[4];
    float* out = (float*)d_out;

    prep_kernel<<<(Bz*Vn*Hf*Wf*Cn)/256, 256>>>(feat, R, T, K, root);
    sample_kernel<<<Bz*Pn/TP, 512>>>(out);
}

// round 4
// speedup vs baseline: 2.0666x; 1.0912x over previous
#include <cuda_runtime.h>

#define Bz 2
#define Vn 4
#define Cn 32
#define Hf 64
#define Wf 64
#define Dv 64
#define Pn (Dv*Dv*Dv)
#define HWC (Hf*Wf*Cn)       // 131072

// Tile: 16 (x) x 4 (y) x 2 (z) = 128 points per block, 512 threads.
#define TX 16
#define TY 4
#define TZ 2
#define TP (TX*TY*TZ)        // 128

__device__ float g_featT[Bz*Vn*Hf*Wf*Cn];   // [BV][H][W][C]
__device__ float g_cam[Bz*Vn][16];

// ---------------------------------------------------------------------------
__global__ void prep_kernel(const float* __restrict__ f,
                            const float* __restrict__ R, const float* __restrict__ T,
                            const float* __restrict__ K, const float* __restrict__ root) {
    int idx = blockIdx.x * blockDim.x + threadIdx.x;
    int c   = idx & 31;
    int pix = (idx >> 5) & (Hf*Wf - 1);
    int bv  = idx >> 17;
    g_featT[idx] = f[(bv*Cn + c)*(Hf*Wf) + pix];

    if (blockIdx.x == 0 && threadIdx.x < Bz*Vn) {
        int i = threadIdx.x, b = i / Vn;
        const float* Ri = R + i*9; const float* Ti = T + i*3;
        const float* Ki = K + i*9; const float* rb = root + b*3;
        float* o = g_cam[i];
        #pragma unroll
        for (int r = 0; r < 9; r++) o[r] = Ri[r];
        #pragma unroll
        for (int r = 0; r < 3; r++)
            o[9+r] = Ri[r*3+0]*rb[0] + Ri[r*3+1]*rb[1] + Ri[r*3+2]*rb[2] + Ti[r];
        o[12] = Ki[0]; o[13] = Ki[4]; o[14] = Ki[2]; o[15] = Ki[5];
    }
}

// ---------------------------------------------------------------------------
// Phase 1: 512 threads project 128 pts x 4 views -> SMEM taps (offsets *Cn,
//          weights with 0.25 view-mean folded).
// Phase 2: warp = 4 point-groups x 8 lanes; lane = 4 channels (float4).
//          Per (iter,view): 1 LDS.128 taps, 4 LDG.128 gathers, 16 FFMA.
// Phase 3: transpose via SMEM, coalesced float4 stores.
// ---------------------------------------------------------------------------
__global__ __launch_bounds__(512, 2) void sample_kernel(float* __restrict__ out) {
    __shared__ int4   s_off[TP][5];          // [pl][v], row-pad 5 -> conflict-free
    __shared__ float4 s_w[TP][5];
    __shared__ float  s_acc[TP][Cn + 1];     // pad 33

    const int tid = threadIdx.x;
    const int bid = blockIdx.x;
    const int b   = bid >> 11;
    const int t   = bid & 2047;
    const int x0t = (t & 3) * TX;
    const int y0t = ((t >> 2) & 15) * TY;
    const int z0t = (t >> 6) * TZ;

    // -------- Phase 1: projection (one (point,view) per thread) --------
    {
        const int pl = tid >> 2;
        const int v  = tid & 3;
        const int xi = x0t + (pl & 15);
        const int yi = y0t + ((pl >> 4) & 3);
        const int zi = z0t + (pl >> 6);

        const float wx = (xi * (1.0f/63.0f) - 0.5f) * 0.2f;
        const float wy = (yi * (1.0f/63.0f) - 0.5f) * 0.2f;
        const float wz = (zi * (1.0f/63.0f) - 0.5f) * 0.2f;

        const float* cam = g_cam[b*Vn + v];
        const float Xc = cam[0]*wx + cam[1]*wy + cam[2]*wz + cam[9];
        const float Yc = cam[3]*wx + cam[4]*wy + cam[5]*wz + cam[10];
        const float Zc = cam[6]*wx + cam[7]*wy + cam[8]*wz + cam[11];
        const float zc = fmaxf(Zc, 1e-5f);

        const float u  = (Xc * cam[12]) / zc + cam[14];
        const float vv = (Yc * cam[13]) / zc + cam[15];
        const float px = u  * (64.0f/255.0f) - 0.5f;
        const float py = vv * (64.0f/255.0f) - 0.5f;

        const float x0f = floorf(px), y0f = floorf(py);
        const float fx1 = px - x0f,   fy1 = py - y0f;
        const float fx0 = 1.0f - fx1, fy0 = 1.0f - fy1;
        const int ix0 = (int)x0f, iy0 = (int)y0f;
        const int ix1 = ix0 + 1,  iy1 = iy0 + 1;

        const float mx0 = (ix0 >= 0 && ix0 < Wf) ? fx0 : 0.0f;
        const float mx1 = (ix1 >= 0 && ix1 < Wf) ? fx1 : 0.0f;
        const float my0 = (iy0 >= 0 && iy0 < Hf) ? fy0 * 0.25f : 0.0f;
        const float my1 = (iy1 >= 0 && iy1 < Hf) ? fy1 * 0.25f : 0.0f;

        const int x0c = min(max(ix0, 0), Wf-1), x1c = min(max(ix1, 0), Wf-1);
        const int y0c = min(max(iy0, 0), Hf-1), y1c = min(max(iy1, 0), Hf-1);

        s_off[pl][v] = make_int4((y0c*Wf + x0c)*Cn, (y0c*Wf + x1c)*Cn,
                                 (y1c*Wf + x0c)*Cn, (y1c*Wf + x1c)*Cn);
        s_w[pl][v]   = make_float4(mx0*my0, mx1*my0, mx0*my1, mx1*my1);
    }
    __syncthreads();

    // -------- Phase 2: channel-vectorized gather --------
    {
        const int w    = tid >> 5;
        const int lane = tid & 31;
        const int g    = lane >> 3;      // point group 0..3
        const int l8   = lane & 7;       // channel quad 0..7
        const int plb  = w * 8;

        float4 acc0 = make_float4(0.f,0.f,0.f,0.f);
        float4 acc1 = make_float4(0.f,0.f,0.f,0.f);
        const float* fbase = g_featT + (size_t)(b*Vn)*HWC + l8*4;

        #pragma unroll
        for (int v = 0; v < Vn; v++) {
            const float* fv = fbase + v*HWC;
            #pragma unroll
            for (int it = 0; it < 2; it++) {
                const int pl = plb + it*4 + g;
                const int4   off = s_off[pl][v];
                const float4 wt  = s_w[pl][v];
                const float4 t0 = __ldg(reinterpret_cast<const float4*>(fv + off.x));
                const float4 t1 = __ldg(reinterpret_cast<const float4*>(fv + off.y));
                const float4 t2 = __ldg(reinterpret_cast<const float4*>(fv + off.z));
                const float4 t3 = __ldg(reinterpret_cast<const float4*>(fv + off.w));
                float4& a = it ? acc1 : acc0;
                a.x = fmaf(wt.x,t0.x, fmaf(wt.y,t1.x, fmaf(wt.z,t2.x, fmaf(wt.w,t3.x, a.x))));
                a.y = fmaf(wt.x,t0.y, fmaf(wt.y,t1.y, fmaf(wt.z,t2.y, fmaf(wt.w,t3.y, a.y))));
                a.z = fmaf(wt.x,t0.z, fmaf(wt.y,t1.z, fmaf(wt.z,t2.z, fmaf(wt.w,t3.z, a.z))));
                a.w = fmaf(wt.x,t0.w, fmaf(wt.y,t1.w, fmaf(wt.z,t2.w, fmaf(wt.w,t3.w, a.w))));
            }
        }
        // conflict-free scalar STS: bank = (pl + 4*l8 + k) mod 32, distinct/warp
        {
            const int pl0 = plb + g;
            const int cb  = l8 * 4;
            s_acc[pl0][cb+0] = acc0.x;  s_acc[pl0][cb+1] = acc0.y;
            s_acc[pl0][cb+2] = acc0.z;  s_acc[pl0][cb+3] = acc0.w;
            const int pl1 = plb + 4 + g;
            s_acc[pl1][cb+0] = acc1.x;  s_acc[pl1][cb+1] = acc1.y;
            s_acc[pl1][cb+2] = acc1.z;  s_acc[pl1][cb+3] = acc1.w;
        }
    }
    __syncthreads();

    // -------- Phase 3: transpose + coalesced float4 stores --------
    #pragma unroll
    for (int q = 0; q < 2; q++) {
        const int idx = q*512 + tid;
        const int xq = idx & 3;
        const int yl = (idx >> 2) & 3;
        const int zl = (idx >> 4) & 1;
        const int c  = idx >> 5;
        const int plb3 = zl*64 + yl*16 + xq*4;
        float4 v;
        v.x = s_acc[plb3+0][c];
        v.y = s_acc[plb3+1][c];
        v.z = s_acc[plb3+2][c];
        v.w = s_acc[plb3+3][c];
        const int pg = (z0t+zl)*4096 + (y0t+yl)*64 + x0t + xq*4;
        *reinterpret_cast<float4*>(out + ((size_t)(b*Cn + c) << 18) + pg) = v;
    }
}

// ---------------------------------------------------------------------------
extern "C" void kernel_launch(void* const* d_in, const int* in_sizes, int n_in,
                              void* d_out, int out_size) {
    const float* feat = (const float*)d_in[0];
    const float* R    = (const float*)d_in[1];
    const float* T    = (const float*)d_in[2];
    const float* K    = (const float*)d_in[3];
    const float* root = (const float*)d_in[4];
    float* out = (float*)d_out;

    prep_kernel<<<(Bz*Vn*Hf*Wf*Cn)/256, 256>>>(feat, R, T, K, root);
    sample_kernel<<<Bz*Pn/TP, 512>>>(out);
}